// round 10
// baseline (speedup 1.0000x reference)
#include <cuda_runtime.h>
#include <cstdint>
#include <math.h>

#define BS   8
#define NT   128
#define CH   1024
#define KH   4
#define HID  512
#define GD   2048
#define NGRP 8
#define MM   1024
#define NCTA 148

// ---- static device scratch ----
__device__ float4 g_Wa[8u*128*128*32];        // Wih frag-packed (67MB)
__device__ uint4  g_Wp[1024u*64*32];          // Whh unit-frag-packed (33.5MB)
__device__ float2 g_Xp[4u*128*128*32];        // inputs frag-packed (16.8MB)
__device__ float2 g_gates[(size_t)NGRP*GD*512]; // [grp][grow][m/2] (67MB)
__device__ float2 g_hbuf[129u*NGRP*2048];     // [t][grp][s*32+l] h history, tf32 (16.9MB)
__device__ float2 g_hout[8u*128*512*4];       // [grp][tt][j][b/2] full-precision h (16.8MB)
__device__ unsigned g_bar;

// ---- helpers ----
__device__ __forceinline__ uint32_t f2tf(float x) {
    uint32_t r; asm("cvt.rna.tf32.f32 %0, %1;" : "=r"(r) : "f"(x)); return r;
}
__device__ __forceinline__ void mma_tf32(float& c0, float& c1, float& c2, float& c3,
                                         uint32_t a0, uint32_t a1, uint32_t a2, uint32_t a3,
                                         uint32_t b0, uint32_t b1) {
    asm volatile("mma.sync.aligned.m16n8k8.row.col.f32.tf32.tf32.f32 "
        "{%0,%1,%2,%3}, {%4,%5,%6,%7}, {%8,%9}, {%0,%1,%2,%3};\n"
        : "+f"(c0), "+f"(c1), "+f"(c2), "+f"(c3)
        : "r"(a0), "r"(a1), "r"(a2), "r"(a3), "r"(b0), "r"(b1));
}
__device__ __forceinline__ float sigm(float x) { return 1.f / (1.f + __expf(-x)); }
__device__ __forceinline__ float tanh_f(float x) { return 2.f / (1.f + __expf(-2.f * x)) - 1.f; }

// ---------------------------------------------------------------------------
__global__ void init_state() {
    int i = blockIdx.x * blockDim.x + threadIdx.x;
    if (i == 0) g_bar = 0u;
    if (i < NGRP * 2048) g_hbuf[i] = make_float2(0.f, 0.f);   // h at t=0
}

// ---------------------------------------------------------------------------
// inputs [b][t][c][k] -> B-frag pack g_Xp (tf32-rounded)
__global__ void pack_inputs(const float* __restrict__ in) {
    int idx = blockIdx.x * blockDim.x + threadIdx.x;
    if (idx >= BS * NT * CH) return;
    int c  = idx % CH;
    int bt = idx / CH;
    int t  = bt % NT;
    int b  = bt / NT;
    float4 v = ((const float4*)in)[idx];
    int m = t * BS + b;
    int mblk = m >> 3, s = c >> 3;
    int l = ((m & 7) << 2) | (c & 3);
    int half = (c >> 2) & 1;
    float* xp = (float*)g_Xp;
    float vv[4] = {v.x, v.y, v.z, v.w};
#pragma unroll
    for (int kk = 0; kk < 4; kk++) {
        size_t fi = ((((size_t)kk * 128 + mblk) * 128 + s) * 32 + l) * 2 + half;
        xp[fi] = __uint_as_float(f2tf(vv[kk]));
    }
}

// ---------------------------------------------------------------------------
__global__ void prepack_Wih(const float* __restrict__ Wih_f, const float* __restrict__ Wih_b) {
    int t = blockIdx.x * blockDim.x + threadIdx.x;
    if (t >= 8 * 128 * 128 * 32) return;
    int l = t & 31, s = (t >> 5) & 127, g16 = (t >> 12) & 127, grp = t >> 19;
    int dir = grp >> 2, kh = grp & 3;
    const float* W = (dir ? Wih_b : Wih_f) + (size_t)kh * GD * CH;
    int r = g16 * 16 + (l >> 2);
    int c = s * 8 + (l & 3);
    float4 v;
    v.x = __uint_as_float(f2tf(W[(size_t)r * CH + c]));
    v.y = __uint_as_float(f2tf(W[(size_t)(r + 8) * CH + c]));
    v.z = __uint_as_float(f2tf(W[(size_t)r * CH + c + 4]));
    v.w = __uint_as_float(f2tf(W[(size_t)(r + 8) * CH + c + 4]));
    g_Wa[t] = v;
}

// ---------------------------------------------------------------------------
// Whh -> per-unit A-frag pack (unit = grp*128+j4 covers 16 rows = 4 gates x 4 j).
__global__ void prepack_Wp(const float* __restrict__ Whh_f, const float* __restrict__ Whh_b) {
    int t = blockIdx.x * blockDim.x + threadIdx.x;   // 1024*64*32
    int l = t & 31, s = (t >> 5) & 63, unit = t >> 11;
    int grp = unit >> 7, j4 = unit & 127;
    int dir = grp >> 2, kh = grp & 3;
    const float* W = (dir ? Whh_b : Whh_f) + (size_t)kh * GD * HID;
    int r = l >> 2;
    int grow0 = (r >> 2) * 512 + j4 * 4 + (r & 3);
    int grow1 = grow0 + 1024;
    int c = s * 8 + (l & 3);
    uint4 v;
    v.x = f2tf(W[(size_t)grow0 * HID + c]);
    v.y = f2tf(W[(size_t)grow1 * HID + c]);
    v.z = f2tf(W[(size_t)grow0 * HID + c + 4]);
    v.w = f2tf(W[(size_t)grow1 * HID + c + 4]);
    g_Wp[t] = v;
}

// ---------------------------------------------------------------------------
// Input GEMM (tf32 mma), frags prepacked. CTA 128g x 128m, 8 warps.
__global__ void __launch_bounds__(256) input_gemm(
    const float* __restrict__ bih_f, const float* __restrict__ bhh_f,
    const float* __restrict__ bih_b, const float* __restrict__ bhh_b)
{
    int grp = blockIdx.z, dir = grp >> 2, kh = grp & 3;
    int tid = threadIdx.x, l = tid & 31, warp = tid >> 5;
    int wm = warp & 3, wn = warp >> 2;
    int t0  = blockIdx.y * 8 + wm * 2;
    int mb0 = blockIdx.x * 16 + wn * 8;

    const uint4*  A0 = (const uint4*)g_Wa + ((size_t)(grp * 128 + t0) * 128) * 32 + l;
    const uint4*  A1 = A0 + 128 * 32;
    const float2* Bp = g_Xp + ((size_t)(kh * 128 + mb0) * 128) * 32 + l;

    float c[2][8][4];
#pragma unroll
    for (int i = 0; i < 2; i++)
#pragma unroll
        for (int j = 0; j < 8; j++)
#pragma unroll
            for (int e = 0; e < 4; e++) c[i][j][e] = 0.f;

#pragma unroll 2
    for (int s = 0; s < 128; s++) {
        uint4 a0 = A0[(size_t)s * 32];
        uint4 a1 = A1[(size_t)s * 32];
        uint32_t bb0[8], bb1[8];
#pragma unroll
        for (int j = 0; j < 8; j++) {
            float2 bv = Bp[(size_t)j * 128 * 32 + (size_t)s * 32];
            bb0[j] = __float_as_uint(bv.x);
            bb1[j] = __float_as_uint(bv.y);
        }
#pragma unroll
        for (int j = 0; j < 8; j++) {
            mma_tf32(c[0][j][0], c[0][j][1], c[0][j][2], c[0][j][3],
                     a0.x, a0.y, a0.z, a0.w, bb0[j], bb1[j]);
            mma_tf32(c[1][j][0], c[1][j][1], c[1][j][2], c[1][j][3],
                     a1.x, a1.y, a1.z, a1.w, bb0[j], bb1[j]);
        }
    }

    const float* bi = (dir ? bih_b : bih_f) + kh * GD;
    const float* bh = (dir ? bhh_b : bhh_f) + kh * GD;
    int r0 = t0 * 16 + (l >> 2);
#pragma unroll
    for (int i = 0; i < 2; i++) {
        int ra = r0 + i * 16, rb = ra + 8;
        float ba = bi[ra] + bh[ra];
        float bbv = bi[rb] + bh[rb];
#pragma unroll
        for (int j = 0; j < 8; j++) {
            int mhalf = (mb0 + j) * 4 + (l & 3);
            g_gates[((size_t)grp * GD + ra) * 512 + mhalf] =
                make_float2(c[i][j][0] + ba, c[i][j][1] + ba);
            g_gates[((size_t)grp * GD + rb) * 512 + mhalf] =
                make_float2(c[i][j][2] + bbv, c[i][j][3] + bbv);
        }
    }
}

// ---------------------------------------------------------------------------
// Persistent recurrent kernel. Single global barrier; dual mma chains;
// NO scattered out-stores in the loop (h goes to g_hout, coalesced).
__global__ void __launch_bounds__(256) lstm_persistent()
{
    extern __shared__ uint4 sW[];
    int tid = threadIdx.x, l = tid & 31, w = tid >> 5;
    int cta = blockIdx.x;
    int nu     = (cta < 136) ? 7 : 6;
    int ustart = (cta < 136) ? cta * 7 : 952 + (cta - 136) * 6;

    // load this CTA's weight units into smem
    {
        uint32_t sb = (uint32_t)__cvta_generic_to_shared(sW);
        const uint4* src = g_Wp + (size_t)ustart * 2048;
        int total = nu * 2048;
        for (int i = tid; i < total; i += 256) {
            asm volatile("cp.async.cg.shared.global [%0], [%1], 16;\n"
                         :: "r"(sb + i * 16), "l"(src + i));
        }
        asm volatile("cp.async.commit_group;\n");
        asm volatile("cp.async.wait_group 0;\n");
    }
    __syncthreads();

    bool active = (w < nu);
    int unit = ustart + (active ? w : 0);
    int grp = unit >> 7, j4 = unit & 127;
    int dir = grp >> 2;

    const uint4* wA = sW + w * 2048 + l;
    int r = l >> 2;
    int ga = (r >> 2) * 512 + j4 * 4 + (r & 3);
    const float2* ginA = g_gates + ((size_t)grp * GD + ga) * 512 + (l & 3);
    const float2* ginB = ginA + (size_t)1024 * 512;

    int jj = r & 3;               // lanes<16: local j
    int b0 = (l & 3) * 2;
    int j  = j4 * 4 + jj;
    int s_ = j4 >> 1, half = j4 & 1;

    float cs0 = 0.f, cs1 = 0.f;

    for (int t = 0; t < NT; t++) {
        int tt = dir ? (NT - 1 - t) : t;

        if (active) {
            // hoist input-gate loads (independent of h)
            float2 ia = __ldg(ginA + tt * 4);
            float2 ib = __ldg(ginB + tt * 4);

            const float2* hrd = g_hbuf + ((size_t)t * NGRP + grp) * 2048 + l;
            float a0c = 0.f, a1c = 0.f, a2c = 0.f, a3c = 0.f;
            float b0c = 0.f, b1c = 0.f, b2c = 0.f, b3c = 0.f;
#pragma unroll 8
            for (int s = 0; s < 32; s++) {
                uint4 aa = wA[s * 32];
                float2 hv = __ldg(hrd + s * 32);
                mma_tf32(a0c, a1c, a2c, a3c, aa.x, aa.y, aa.z, aa.w,
                         __float_as_uint(hv.x), __float_as_uint(hv.y));
                uint4 ab = wA[(s + 32) * 32];
                float2 hw2 = __ldg(hrd + (s + 32) * 32);
                mma_tf32(b0c, b1c, b2c, b3c, ab.x, ab.y, ab.z, ab.w,
                         __float_as_uint(hw2.x), __float_as_uint(hw2.y));
            }
            float c0 = a0c + b0c + ia.x;
            float c1 = a1c + b1c + ia.y;
            float c2 = a2c + b2c + ib.x;
            float c3 = a3c + b3c + ib.y;

            float r0 = __shfl_xor_sync(0xffffffffu, c0, 16);
            float r1 = __shfl_xor_sync(0xffffffffu, c1, 16);
            float r2 = __shfl_xor_sync(0xffffffffu, c2, 16);
            float r3 = __shfl_xor_sync(0xffffffffu, c3, 16);

            if (l < 16) {
                float i0 = sigm(c0), f0 = sigm(r0), g0 = tanh_f(c2), o0 = sigm(r2);
                cs0 = f0 * cs0 + i0 * g0;
                float hn0 = o0 * tanh_f(cs0);
                float i1 = sigm(c1), f1 = sigm(r1), g1 = tanh_f(c3), o1 = sigm(r3);
                cs1 = f1 * cs1 + i1 * g1;
                float hn1 = o1 * tanh_f(cs1);

                // recurrence buffer (tf32-rounded, frag layout)
                float* hw = (float*)(g_hbuf + ((size_t)(t + 1) * NGRP + grp) * 2048 + s_ * 32);
                hw[((b0 << 2) | jj) * 2 + half]       = __uint_as_float(f2tf(hn0));
                hw[(((b0 + 1) << 2) | jj) * 2 + half] = __uint_as_float(f2tf(hn1));

                // full-precision output history: [grp][tt][j][b/2] (coalesced 256B/warp)
                g_hout[(((size_t)grp * NT + tt) * HID + j) * 4 + (b0 >> 1)] =
                    make_float2(hn0, hn1);
            }
        }

        if (t < NT - 1) {
            __threadfence();
            __syncthreads();
            if (tid == 0) {
                atomicAdd(&g_bar, 1u);
                unsigned target = (unsigned)NCTA * (t + 1);
                unsigned v;
                do {
                    asm volatile("ld.global.acquire.gpu.b32 %0, [%1];"
                                 : "=r"(v) : "l"(&g_bar));
                } while (v < target);
            }
            __syncthreads();
        }
    }
}

// ---------------------------------------------------------------------------
// Post-pass: gather 4 heads -> float4, write out[b][tt][dir*512+j][k].
__global__ void write_out(float* __restrict__ out) {
    int idx = blockIdx.x * blockDim.x + threadIdx.x;   // 8*128*2*512 = 1M
    int j   = idx & 511;
    int dir = (idx >> 9) & 1;
    int tt  = (idx >> 10) & 127;
    int b   = idx >> 17;
    const float* hb = (const float*)g_hout;
    float4 v;
    size_t base = (((size_t)(dir * 4) * NT + tt) * HID + j) * 8 + b;
    v.x = hb[base];
    v.y = hb[base + (size_t)NT * HID * 8];
    v.z = hb[base + (size_t)2 * NT * HID * 8];
    v.w = hb[base + (size_t)3 * NT * HID * 8];
    ((float4*)out)[((size_t)b * NT + tt) * 1024 + dir * 512 + j] = v;
}

// ---------------------------------------------------------------------------
extern "C" void kernel_launch(void* const* d_in, const int* in_sizes, int n_in,
                              void* d_out, int out_size) {
    const float* inputs = (const float*)d_in[0];
    const float* Wih_f  = (const float*)d_in[1];
    const float* Whh_f  = (const float*)d_in[2];
    const float* bih_f  = (const float*)d_in[3];
    const float* bhh_f  = (const float*)d_in[4];
    const float* Wih_b  = (const float*)d_in[5];
    const float* Whh_b  = (const float*)d_in[6];
    const float* bih_b  = (const float*)d_in[7];
    const float* bhh_b  = (const float*)d_in[8];
    float* out = (float*)d_out;

    const int SMEM_BYTES = 7 * 2048 * 16;   // 229376
    cudaFuncSetAttribute(lstm_persistent, cudaFuncAttributeMaxDynamicSharedMemorySize, SMEM_BYTES);

    init_state<<<64, 256>>>();
    pack_inputs<<<(BS * NT * CH + 255) / 256, 256>>>(inputs);
    prepack_Wih<<<(8 * 128 * 128 * 32) / 256, 256>>>(Wih_f, Wih_b);
    prepack_Wp<<<(1024 * 64 * 32) / 256, 256>>>(Whh_f, Whh_b);

    input_gemm<<<dim3(8, 16, 8), 256>>>(bih_f, bhh_f, bih_b, bhh_b);

    lstm_persistent<<<NCTA, 256, SMEM_BYTES>>>();
    write_out<<<(8 * 128 * 2 * 512) / 256, 256>>>(out);
}

// round 11
// speedup vs baseline: 1.1718x; 1.1718x over previous
#include <cuda_runtime.h>
#include <cstdint>
#include <math.h>

#define BS   8
#define NT   128
#define CH   1024
#define KH   4
#define HID  512
#define GD   2048
#define NGRP 8
#define MM   1024
#define NCTA 148

// ---- static device scratch ----
__device__ float4 g_Wa[8u*128*128*32];        // Wih frag-packed (67MB)
__device__ uint4  g_Wp[1024u*64*32];          // Whh unit-frag-packed (33.5MB)
__device__ float2 g_Xp[4u*128*128*32];        // inputs frag-packed (16.8MB)
__device__ float2 g_gates[(size_t)NGRP*GD*512]; // [grp][grow][m/2] (67MB)
__device__ float2 g_hbuf[129u*NGRP*2048];     // [t][grp][s*32+l] h history, tf32 (16.9MB)
__device__ float4 g_part[NCTA*7*32];          // k-split partial exchange (132KB)
__device__ unsigned g_bar;

// ---- helpers ----
__device__ __forceinline__ uint32_t f2tf(float x) {
    uint32_t r; asm("cvt.rna.tf32.f32 %0, %1;" : "=r"(r) : "f"(x)); return r;
}
__device__ __forceinline__ void mma_tf32(float& c0, float& c1, float& c2, float& c3,
                                         uint32_t a0, uint32_t a1, uint32_t a2, uint32_t a3,
                                         uint32_t b0, uint32_t b1) {
    asm volatile("mma.sync.aligned.m16n8k8.row.col.f32.tf32.tf32.f32 "
        "{%0,%1,%2,%3}, {%4,%5,%6,%7}, {%8,%9}, {%0,%1,%2,%3};\n"
        : "+f"(c0), "+f"(c1), "+f"(c2), "+f"(c3)
        : "r"(a0), "r"(a1), "r"(a2), "r"(a3), "r"(b0), "r"(b1));
}
__device__ __forceinline__ float sigm(float x) { return 1.f / (1.f + __expf(-x)); }
__device__ __forceinline__ float tanh_f(float x) { return 2.f / (1.f + __expf(-2.f * x)) - 1.f; }

// ---------------------------------------------------------------------------
__global__ void init_state() {
    int i = blockIdx.x * blockDim.x + threadIdx.x;
    if (i == 0) g_bar = 0u;
    if (i < NGRP * 2048) g_hbuf[i] = make_float2(0.f, 0.f);   // h at t=0
}

// ---------------------------------------------------------------------------
// inputs [b][t][c][k] -> B-frag pack g_Xp (tf32-rounded)
__global__ void pack_inputs(const float* __restrict__ in) {
    int idx = blockIdx.x * blockDim.x + threadIdx.x;
    if (idx >= BS * NT * CH) return;
    int c  = idx % CH;
    int bt = idx / CH;
    int t  = bt % NT;
    int b  = bt / NT;
    float4 v = ((const float4*)in)[idx];
    int m = t * BS + b;
    int mblk = m >> 3, s = c >> 3;
    int l = ((m & 7) << 2) | (c & 3);
    int half = (c >> 2) & 1;
    float* xp = (float*)g_Xp;
    float vv[4] = {v.x, v.y, v.z, v.w};
#pragma unroll
    for (int kk = 0; kk < 4; kk++) {
        size_t fi = ((((size_t)kk * 128 + mblk) * 128 + s) * 32 + l) * 2 + half;
        xp[fi] = __uint_as_float(f2tf(vv[kk]));
    }
}

// ---------------------------------------------------------------------------
__global__ void prepack_Wih(const float* __restrict__ Wih_f, const float* __restrict__ Wih_b) {
    int t = blockIdx.x * blockDim.x + threadIdx.x;
    if (t >= 8 * 128 * 128 * 32) return;
    int l = t & 31, s = (t >> 5) & 127, g16 = (t >> 12) & 127, grp = t >> 19;
    int dir = grp >> 2, kh = grp & 3;
    const float* W = (dir ? Wih_b : Wih_f) + (size_t)kh * GD * CH;
    int r = g16 * 16 + (l >> 2);
    int c = s * 8 + (l & 3);
    float4 v;
    v.x = __uint_as_float(f2tf(W[(size_t)r * CH + c]));
    v.y = __uint_as_float(f2tf(W[(size_t)(r + 8) * CH + c]));
    v.z = __uint_as_float(f2tf(W[(size_t)r * CH + c + 4]));
    v.w = __uint_as_float(f2tf(W[(size_t)(r + 8) * CH + c + 4]));
    g_Wa[t] = v;
}

// ---------------------------------------------------------------------------
// Whh -> per-unit A-frag pack (unit = grp*128+j4 covers 16 rows = 4 gates x 4 j).
__global__ void prepack_Wp(const float* __restrict__ Whh_f, const float* __restrict__ Whh_b) {
    int t = blockIdx.x * blockDim.x + threadIdx.x;   // 1024*64*32
    int l = t & 31, s = (t >> 5) & 63, unit = t >> 11;
    int grp = unit >> 7, j4 = unit & 127;
    int dir = grp >> 2, kh = grp & 3;
    const float* W = (dir ? Whh_b : Whh_f) + (size_t)kh * GD * HID;
    int r = l >> 2;
    int grow0 = (r >> 2) * 512 + j4 * 4 + (r & 3);
    int grow1 = grow0 + 1024;
    int c = s * 8 + (l & 3);
    uint4 v;
    v.x = f2tf(W[(size_t)grow0 * HID + c]);
    v.y = f2tf(W[(size_t)grow1 * HID + c]);
    v.z = f2tf(W[(size_t)grow0 * HID + c + 4]);
    v.w = f2tf(W[(size_t)grow1 * HID + c + 4]);
    g_Wp[t] = v;
}

// ---------------------------------------------------------------------------
// Input GEMM (tf32 mma), frags prepacked. CTA 128g x 128m, 8 warps.
__global__ void __launch_bounds__(256) input_gemm(
    const float* __restrict__ bih_f, const float* __restrict__ bhh_f,
    const float* __restrict__ bih_b, const float* __restrict__ bhh_b)
{
    int grp = blockIdx.z, dir = grp >> 2, kh = grp & 3;
    int tid = threadIdx.x, l = tid & 31, warp = tid >> 5;
    int wm = warp & 3, wn = warp >> 2;
    int t0  = blockIdx.y * 8 + wm * 2;
    int mb0 = blockIdx.x * 16 + wn * 8;

    const uint4*  A0 = (const uint4*)g_Wa + ((size_t)(grp * 128 + t0) * 128) * 32 + l;
    const uint4*  A1 = A0 + 128 * 32;
    const float2* Bp = g_Xp + ((size_t)(kh * 128 + mb0) * 128) * 32 + l;

    float c[2][8][4];
#pragma unroll
    for (int i = 0; i < 2; i++)
#pragma unroll
        for (int j = 0; j < 8; j++)
#pragma unroll
            for (int e = 0; e < 4; e++) c[i][j][e] = 0.f;

#pragma unroll 2
    for (int s = 0; s < 128; s++) {
        uint4 a0 = A0[(size_t)s * 32];
        uint4 a1 = A1[(size_t)s * 32];
        uint32_t bb0[8], bb1[8];
#pragma unroll
        for (int j = 0; j < 8; j++) {
            float2 bv = Bp[(size_t)j * 128 * 32 + (size_t)s * 32];
            bb0[j] = __float_as_uint(bv.x);
            bb1[j] = __float_as_uint(bv.y);
        }
#pragma unroll
        for (int j = 0; j < 8; j++) {
            mma_tf32(c[0][j][0], c[0][j][1], c[0][j][2], c[0][j][3],
                     a0.x, a0.y, a0.z, a0.w, bb0[j], bb1[j]);
            mma_tf32(c[1][j][0], c[1][j][1], c[1][j][2], c[1][j][3],
                     a1.x, a1.y, a1.z, a1.w, bb0[j], bb1[j]);
        }
    }

    const float* bi = (dir ? bih_b : bih_f) + kh * GD;
    const float* bh = (dir ? bhh_b : bhh_f) + kh * GD;
    int r0 = t0 * 16 + (l >> 2);
#pragma unroll
    for (int i = 0; i < 2; i++) {
        int ra = r0 + i * 16, rb = ra + 8;
        float ba = bi[ra] + bh[ra];
        float bbv = bi[rb] + bh[rb];
#pragma unroll
        for (int j = 0; j < 8; j++) {
            int mhalf = (mb0 + j) * 4 + (l & 3);
            g_gates[((size_t)grp * GD + ra) * 512 + mhalf] =
                make_float2(c[i][j][0] + ba, c[i][j][1] + ba);
            g_gates[((size_t)grp * GD + rb) * 512 + mhalf] =
                make_float2(c[i][j][2] + bbv, c[i][j][3] + bbv);
        }
    }
}

// ---------------------------------------------------------------------------
// Persistent recurrent kernel, 512 threads: warp pair (2u, 2u+1) splits unit
// u's k=512 into two halves (chain 64->32, 2x warps for latency cover).
// Odd warp writes its partial to g_part; even warp sums, does cell + stores
// (identical to R7). Single global barrier (R7-proven).
__global__ void __launch_bounds__(512) lstm_persistent(float* __restrict__ out)
{
    extern __shared__ uint4 sW[];
    int tid = threadIdx.x, l = tid & 31, w = tid >> 5;
    int cta = blockIdx.x;
    int nu     = (cta < 136) ? 7 : 6;
    int ustart = (cta < 136) ? cta * 7 : 952 + (cta - 136) * 6;

    // load this CTA's weight units into smem
    {
        uint32_t sb = (uint32_t)__cvta_generic_to_shared(sW);
        const uint4* src = g_Wp + (size_t)ustart * 2048;
        int total = nu * 2048;
        for (int i = tid; i < total; i += 512) {
            asm volatile("cp.async.cg.shared.global [%0], [%1], 16;\n"
                         :: "r"(sb + i * 16), "l"(src + i));
        }
        asm volatile("cp.async.commit_group;\n");
        asm volatile("cp.async.wait_group 0;\n");
    }
    __syncthreads();

    int uu = w >> 1, khalf = w & 1;
    bool active = (uu < nu);
    int unit = ustart + (active ? uu : 0);
    int grp = unit >> 7, j4 = unit & 127;
    int dir = grp >> 2, kh = grp & 3;

    const uint4* wA = sW + uu * 2048 + khalf * 1024 + l;
    int r = l >> 2;
    int ga = (r >> 2) * 512 + j4 * 4 + (r & 3);
    const float2* ginA = g_gates + ((size_t)grp * GD + ga) * 512 + (l & 3);
    const float2* ginB = ginA + (size_t)1024 * 512;

    float4* pbuf = g_part + ((size_t)cta * 7 + uu) * 32;

    int jj = r & 3;               // lanes<16: local j
    int b0 = (l & 3) * 2;
    int j  = j4 * 4 + jj;
    int s_ = j4 >> 1, half = j4 & 1;

    float cs0 = 0.f, cs1 = 0.f;

    for (int t = 0; t < NT; t++) {
        int tt = dir ? (NT - 1 - t) : t;
        float c0 = 0.f, c1 = 0.f, c2 = 0.f, c3 = 0.f;

        if (active) {
            const float2* hrd = g_hbuf + ((size_t)t * NGRP + grp) * 2048
                                + khalf * 1024 + l;
#pragma unroll 8
            for (int s = 0; s < 32; s++) {
                uint4 a = wA[s * 32];
                float2 hv = __ldg(hrd + s * 32);
                mma_tf32(c0, c1, c2, c3, a.x, a.y, a.z, a.w,
                         __float_as_uint(hv.x), __float_as_uint(hv.y));
            }
            if (khalf) pbuf[l] = make_float4(c0, c1, c2, c3);
        }
        __syncthreads();   // partials visible block-wide (same-L1 coherence)

        if (active && khalf == 0) {
            float4 p = pbuf[l];
            float2 ia = __ldg(ginA + tt * 4);
            float2 ib = __ldg(ginB + tt * 4);
            c0 += p.x + ia.x;
            c1 += p.y + ia.y;
            c2 += p.z + ib.x;
            c3 += p.w + ib.y;

            float r0 = __shfl_xor_sync(0xffffffffu, c0, 16);
            float r1 = __shfl_xor_sync(0xffffffffu, c1, 16);
            float r2 = __shfl_xor_sync(0xffffffffu, c2, 16);
            float r3 = __shfl_xor_sync(0xffffffffu, c3, 16);

            if (l < 16) {
                float i0 = sigm(c0), f0 = sigm(r0), g0 = tanh_f(c2), o0 = sigm(r2);
                cs0 = f0 * cs0 + i0 * g0;
                float hn0 = o0 * tanh_f(cs0);
                float i1 = sigm(c1), f1 = sigm(r1), g1 = tanh_f(c3), o1 = sigm(r3);
                cs1 = f1 * cs1 + i1 * g1;
                float hn1 = o1 * tanh_f(cs1);

                float* hw = (float*)(g_hbuf + ((size_t)(t + 1) * NGRP + grp) * 2048 + s_ * 32);
                hw[((b0 << 2) | jj) * 2 + half]       = __uint_as_float(f2tf(hn0));
                hw[(((b0 + 1) << 2) | jj) * 2 + half] = __uint_as_float(f2tf(hn1));

                out[(((size_t)b0 * NT + tt) * (2 * HID) + dir * HID + j) * KH + kh] = hn0;
                out[(((size_t)(b0 + 1) * NT + tt) * (2 * HID) + dir * HID + j) * KH + kh] = hn1;
            }
        }

        if (t < NT - 1) {
            __threadfence();
            __syncthreads();
            if (tid == 0) {
                atomicAdd(&g_bar, 1u);
                unsigned target = (unsigned)NCTA * (t + 1);
                unsigned v;
                do {
                    asm volatile("ld.global.acquire.gpu.b32 %0, [%1];"
                                 : "=r"(v) : "l"(&g_bar));
                } while (v < target);
            }
            __syncthreads();
        }
    }
}

// ---------------------------------------------------------------------------
extern "C" void kernel_launch(void* const* d_in, const int* in_sizes, int n_in,
                              void* d_out, int out_size) {
    const float* inputs = (const float*)d_in[0];
    const float* Wih_f  = (const float*)d_in[1];
    const float* Whh_f  = (const float*)d_in[2];
    const float* bih_f  = (const float*)d_in[3];
    const float* bhh_f  = (const float*)d_in[4];
    const float* Wih_b  = (const float*)d_in[5];
    const float* Whh_b  = (const float*)d_in[6];
    const float* bih_b  = (const float*)d_in[7];
    const float* bhh_b  = (const float*)d_in[8];
    float* out = (float*)d_out;

    const int SMEM_BYTES = 7 * 2048 * 16;   // 229376
    cudaFuncSetAttribute(lstm_persistent, cudaFuncAttributeMaxDynamicSharedMemorySize, SMEM_BYTES);

    init_state<<<64, 256>>>();
    pack_inputs<<<(BS * NT * CH + 255) / 256, 256>>>(inputs);
    prepack_Wih<<<(8 * 128 * 128 * 32) / 256, 256>>>(Wih_f, Wih_b);
    prepack_Wp<<<(1024 * 64 * 32) / 256, 256>>>(Whh_f, Whh_b);

    input_gemm<<<dim3(8, 16, 8), 256>>>(bih_f, bhh_f, bih_b, bhh_b);

    lstm_persistent<<<NCTA, 512, SMEM_BYTES>>>(out);
}